// round 14
// baseline (speedup 1.0000x reference)
#include <cuda_runtime.h>
#include <cuda_fp16.h>
#include <math.h>
#include <float.h>
#include <stdint.h>

// Problem dims
#define BATCH    16384
#define IN_C     128
#define CH       512
#define EMBED_D  6240
#define NUM_EMB  512
#define DEC_IN   64
#define DATA_Y   32

// Output layout (float32): dec[B*32], diff[1], embed_ind[B], perplexity[1]
#define OUT_DIFF  (BATCH * DATA_Y)
#define OUT_IND   (OUT_DIFF + 1)
#define OUT_PERP  (OUT_IND + BATCH)

#define MAXFLAG 16384
#define MARGIN  2.0f

#define NSPLIT  26
#define KCHUNK  240           // 26 * 240 = 6240
#define NCHUNKD 195
#define DCHUNK  32
#define NCHUNKG 5
#define GCHUNK  1248

// ---------------- scratch (device globals) ----------------
__device__ __align__(16) uint32_t g_h1hi[BATCH * 512];
__device__ __align__(16) uint32_t g_h1lo[BATCH * 512];
__device__ __align__(16) float  g_S [BATCH * 512];
__device__ __align__(16) float  g_expad[BATCH * 128];
__device__ __align__(16) float  g_part[NSPLIT * 1024 * CH];
__device__ __align__(16) float  g_MGT [1024 * CH];
__device__ __align__(16) uint32_t g_MGThi[1024 * 256];
__device__ __align__(16) __half g_BcatTh[1024 * EMBED_D];
__device__ __align__(16) __half g_BcatTl[1024 * EMBED_D];
__device__ __align__(16) __half g_Wf2h[CH * EMBED_D];
__device__ __align__(16) __half g_Wf2l[CH * EMBED_D];
__device__ __align__(16) __half g_xh[BATCH * IN_C];
__device__ __align__(16) __half g_xl[BATCH * IN_C];
__device__ __align__(16) __half g_B1h[1024 * IN_C];
__device__ __align__(16) __half g_B1l[1024 * IN_C];
__device__ __align__(16) __half g_Wx2h[128 * CH];
__device__ __align__(16) __half g_Wx2l[128 * CH];
__device__ float  g_bx2pad[128];
__device__ float  g_biascat1[1024];
__device__ float  g_bias2[1024];
__device__ float  g_e2[NUM_EMB];
__device__ double g_e2d[NUM_EMB];
__device__ double g_cd[NUM_EMB];
__device__ float  g_beta;
__device__ double g_sum;
__device__ int    g_ind[BATCH];
__device__ double g_pc [NCHUNKD * NUM_EMB];
__device__ double g_pe2[NCHUNKD * NUM_EMB];
__device__ double g_pg [NCHUNKG * CH];
__device__ int    g_counts[NUM_EMB];
__device__ int    g_woff[NUM_EMB];
__device__ int    g_order[BATCH];
__device__ int    g_nflag;
__device__ int    g_fb [MAXFLAG];
__device__ int    g_fk1[MAXFLAG];
__device__ int    g_fk2[MAXFLAG];

// ------------------------ helpers ------------------------
__device__ __forceinline__ uint32_t pack2(float a, float b) {
    __half2 h = __floats2half2_rn(a, b);
    return *reinterpret_cast<uint32_t*>(&h);
}
__device__ __forceinline__ void hilo2(float a, float b, uint32_t& hi, uint32_t& lo) {
    __half ha = __float2half_rn(a), hb = __float2half_rn(b);
    float la = a - __half2float(ha);
    float lb = b - __half2float(hb);
    __half2 h = __halves2half2(ha, hb);
    hi = *reinterpret_cast<uint32_t*>(&h);
    lo = pack2(la, lb);
}
__device__ __forceinline__ void mma16(float* c, const uint32_t* a,
                                      uint32_t b0, uint32_t b1) {
    asm volatile("mma.sync.aligned.m16n8k16.row.col.f32.f16.f16.f32 "
        "{%0,%1,%2,%3}, {%4,%5,%6,%7}, {%8,%9}, {%0,%1,%2,%3};"
        : "+f"(c[0]), "+f"(c[1]), "+f"(c[2]), "+f"(c[3])
        : "r"(a[0]), "r"(a[1]), "r"(a[2]), "r"(a[3]), "r"(b0), "r"(b1));
}
__device__ __forceinline__ uint32_t cvta_smem(const void* p) {
    uint32_t a;
    asm("{ .reg .u64 t; cvta.to.shared.u64 t, %1; cvt.u32.u64 %0, t; }"
        : "=r"(a) : "l"(p));
    return a;
}
#define CP_ASYNC16(dst, src) \
    asm volatile("cp.async.ca.shared.global [%0], [%1], 16;" \
                 :: "r"(dst), "l"(src) : "memory")
#define CP_COMMIT() asm volatile("cp.async.commit_group;" ::: "memory")
template<int N>
__device__ __forceinline__ void cp_wait() {
    asm volatile("cp.async.wait_group %0;" :: "n"(N) : "memory");
}
__device__ __forceinline__ void ldm_x4(uint32_t* r, uint32_t addr) {
    asm volatile("ldmatrix.sync.aligned.m8n8.x4.shared.b16 {%0,%1,%2,%3}, [%4];"
        : "=r"(r[0]), "=r"(r[1]), "=r"(r[2]), "=r"(r[3]) : "r"(addr));
}

// stage block: 128 rows x 12 u32 (stride 12 => conflict-free ldmatrix) = 6144 B
#define STG_BYTES 6144

// ============================ mega-prep =====================================
#define J_EMBT   3120
#define J_WF2    (J_EMBT + 3120)
#define J_B1T    (J_WF2 + 128)
#define J_WX2    (J_B1T + 64)
#define J_TOT    (J_WX2 + 1)
__global__ void prep1_kernel(const float* __restrict__ embed,
                             const float* __restrict__ Wf2,
                             const float* __restrict__ Wf1,
                             const float* __restrict__ Wx1,
                             const float* __restrict__ bf1,
                             const float* __restrict__ bx1,
                             const float* __restrict__ Wx2,
                             const float* __restrict__ bx2) {
    __shared__ float t[32][33];
    const int bi = blockIdx.x;
    const int tid = threadIdx.x;
    const int tx = tid & 31, ty = tid >> 5;

    if (bi < J_EMBT) {
        int d0 = (bi % 195) * 32;
        int k0 = (bi / 195) * 32;
        #pragma unroll
        for (int r = 0; r < 32; r += 8)
            t[ty + r][tx] = embed[(size_t)(d0 + ty + r) * 512 + k0 + tx];
        __syncthreads();
        #pragma unroll
        for (int r = 0; r < 32; r += 8) {
            float v = t[tx][ty + r];
            __half h = __float2half_rn(v);
            size_t o = (size_t)(k0 + ty + r) * EMBED_D + d0 + tx;
            g_BcatTh[o] = h;
            g_BcatTl[o] = __float2half_rn(v - __half2float(h));
        }
    } else if (bi < J_WF2) {
        size_t i = (size_t)(bi - J_EMBT) * 256 + tid;
        float4 v = reinterpret_cast<const float4*>(Wf2)[i];
        uint32_t h0, l0, h1, l1;
        hilo2(v.x, v.y, h0, l0);
        hilo2(v.z, v.w, h1, l1);
        uint2 uh = {h0, h1}, ul = {l0, l1};
        reinterpret_cast<uint2*>(g_Wf2h)[i] = uh;
        reinterpret_cast<uint2*>(g_Wf2l)[i] = ul;
        reinterpret_cast<uint2*>(g_BcatTh)[798720 + i] = uh;
        reinterpret_cast<uint2*>(g_BcatTl)[798720 + i] = ul;
    } else if (bi < J_B1T) {
        int b2 = bi - J_WF2;
        int n0 = (b2 & 31) * 32;
        int k0 = (b2 >> 5) * 32;
        #pragma unroll
        for (int r = 0; r < 32; r += 8) {
            int n = n0 + tx;
            t[ty + r][tx] = (n < 512)
                ? Wf1[(size_t)(k0 + ty + r) * 512 + n]
                : Wx1[(size_t)(k0 + ty + r) * 512 + n - 512];
        }
        __syncthreads();
        #pragma unroll
        for (int r = 0; r < 32; r += 8) {
            float v = t[tx][ty + r];
            __half h = __float2half_rn(v);
            size_t o = (size_t)(n0 + ty + r) * IN_C + k0 + tx;
            g_B1h[o] = h;
            g_B1l[o] = __float2half_rn(v - __half2float(h));
        }
    } else if (bi < J_WX2) {
        int base = (bi - J_B1T) * 1024 + tid * 4;
        float vv[4];
        #pragma unroll
        for (int j = 0; j < 4; j++) {
            int idx = base + j;
            int n = idx >> 9, k = idx & 511;
            vv[j] = (n < 64) ? Wx2[(size_t)k * 64 + n] : 0.f;
        }
        uint32_t h0, l0, h1, l1;
        hilo2(vv[0], vv[1], h0, l0);
        hilo2(vv[2], vv[3], h1, l1);
        reinterpret_cast<uint2*>(g_Wx2h)[base >> 2] = {h0, h1};
        reinterpret_cast<uint2*>(g_Wx2l)[base >> 2] = {l0, l1};
        if (bi == J_B1T && tid < 128)
            g_bx2pad[tid] = (tid < 64) ? bx2[tid] : 0.f;
    } else {
        #pragma unroll
        for (int j = 0; j < 4; j++) {
            int k = tid + j * 256;
            g_biascat1[k] = (k < 512) ? bf1[k] : bx1[k - 512];
        }
        g_counts[tid] = 0;
        g_counts[tid + 256] = 0;
        if (tid == 0) { g_sum = 0.0; g_nflag = 0; }
    }
}

__global__ void xsplit_kernel(const float* __restrict__ x) {
    size_t i = (size_t)blockIdx.x * 256 + threadIdx.x;
    float4 v = reinterpret_cast<const float4*>(x)[i];
    uint32_t h0, l0, h1, l1;
    hilo2(v.x, v.y, h0, l0);
    hilo2(v.z, v.w, h1, l1);
    reinterpret_cast<uint2*>(g_xh)[i] = {h0, h1};
    reinterpret_cast<uint2*>(g_xl)[i] = {l0, l1};
}

// ---------------- prep2: vq partials + g partials + beta ---------------------
__global__ void prep2_kernel(const float* __restrict__ embed,
                             const float* __restrict__ Wf2,
                             const float* __restrict__ bf2) {
    const int bi = blockIdx.x;
    if (bi < NCHUNKD) {
        int k = threadIdx.x;
        int d0 = bi * DCHUNK;
        double cc = 0.0, ee = 0.0;
        for (int d = d0; d < d0 + DCHUNK; d++) {
            double e = (double)embed[(size_t)d * NUM_EMB + k];
            cc += (double)bf2[d] * e;
            ee += e * e;
        }
        g_pc [bi * NUM_EMB + k] = cc;
        g_pe2[bi * NUM_EMB + k] = ee;
    } else if (bi < NCHUNKD + 160) {
        int gw = (bi - NCHUNKD) * 16 + (threadIdx.x >> 5);
        int lane = threadIdx.x & 31;
        int i = gw % CH;
        int c = gw / CH;
        const float* w = Wf2 + (size_t)i * EMBED_D + c * GCHUNK;
        const float* b = bf2 + c * GCHUNK;
        double s = 0.0;
        #pragma unroll 4
        for (int t = lane; t < GCHUNK; t += 32)
            s += (double)w[t] * (double)b[t];
        #pragma unroll
        for (int o = 16; o; o >>= 1) s += __shfl_xor_sync(0xFFFFFFFFu, s, o);
        if (lane == 0) g_pg[c * CH + i] = s;
    } else {
        __shared__ double red[512];
        double s = 0.0;
        for (int d = threadIdx.x; d < EMBED_D; d += 512) { double v = bf2[d]; s += v * v; }
        red[threadIdx.x] = s;
        __syncthreads();
        for (int t = 256; t; t >>= 1) {
            if (threadIdx.x < t) red[threadIdx.x] += red[threadIdx.x + t];
            __syncthreads();
        }
        if (threadIdx.x == 0) g_beta = (float)red[0];
    }
}

__global__ void prep3_kernel() {
    int k = threadIdx.x;
    if (k < 512) {
        double cc = 0.0, ee = 0.0;
        for (int s = 0; s < NCHUNKD; s++) {
            cc += g_pc [s * NUM_EMB + k];
            ee += g_pe2[s * NUM_EMB + k];
        }
        g_bias2[k] = (float)cc;
        g_cd[k]  = cc;
        g_e2[k]  = (float)ee;
        g_e2d[k] = ee;
    } else {
        int i = k - 512;
        double s = 0.0;
        #pragma unroll
        for (int c = 0; c < NCHUNKG; c++) s += g_pg[c * CH + i];
        g_bias2[512 + i] = (float)(2.0 * s);
    }
}

// ====== multistage HMMA GEMM (cp.async ring + ldmatrix): C = op(A@Bt^T) ======
template<bool X3, int STAGES, int EPI, bool HASBIAS, bool RELU, bool SPLITK>
__global__ void __launch_bounds__(256)
hgemm(const __half* __restrict__ Ah, const __half* __restrict__ Al,
      const __half* __restrict__ Bh, const __half* __restrict__ Bl,
      const float* __restrict__ bias, float* __restrict__ C, float* __restrict__ C2,
      int M, int N, int K, int lda, int ldb, int ldc, int m_off) {
    constexpr int NOPS = X3 ? 2 : 1;
    extern __shared__ uint32_t sm[];
    const uint32_t smBase = cvta_smem(sm);
    const int tid  = threadIdx.x;
    const int lane = tid & 31;
    const int wid  = tid >> 5;
    const int n0 = blockIdx.x * 128;
    const int m0 = m_off + blockIdx.y * 128;
    if (SPLITK) {
        Ah += blockIdx.z * KCHUNK;  Bh += blockIdx.z * KCHUNK;
        if (X3) { Al += blockIdx.z * KCHUNK;  Bl += blockIdx.z * KCHUNK; }
        C  += (size_t)blockIdx.z * M * N;
        K = KCHUNK;
    }
    const int wm = (wid & 3) * 32;
    const int wn = (wid >> 2) * 64;
    const int lq = lane >> 2;
    const int lr = lane & 3;

    float acc[2][8][4];
    #pragma unroll
    for (int mi = 0; mi < 2; mi++)
        #pragma unroll
        for (int ni = 0; ni < 8; ni++)
            #pragma unroll
            for (int j = 0; j < 4; j++) acc[mi][ni][j] = 0.f;

    const int lrow = tid >> 1;
    const int lkh  = tid & 1;
    const __half* aps[2]; aps[0] = Ah; aps[1] = X3 ? Al : Ah;
    const __half* bps[2]; bps[0] = Bh; bps[1] = X3 ? Bl : Bh;

    uint32_t aDst0[NOPS], bDst0[NOPS];
    #pragma unroll
    for (int op = 0; op < NOPS; op++) {
        aDst0[op] = smBase + op * STAGES * STG_BYTES + (lrow * 12 + lkh * 4) * 4;
        bDst0[op] = smBase + (NOPS + op) * STAGES * STG_BYTES + (lrow * 12 + lkh * 4) * 4;
    }
    const int amRow = wm + (lane & 15);
    const int akh   = lane >> 4;
    uint32_t aF0[NOPS][2];
    #pragma unroll
    for (int op = 0; op < NOPS; op++) {
        aF0[op][0] = smBase + op * STAGES * STG_BYTES + (amRow * 12 + akh * 4) * 4;
        aF0[op][1] = aF0[op][0] + 16 * 48;
    }
    const int bnRow = wn + (lane & 7) + ((lane & 16) >> 1);
    const int bkh   = (lane >> 3) & 1;
    uint32_t bF0[NOPS];
    #pragma unroll
    for (int op = 0; op < NOPS; op++)
        bF0[op] = smBase + (NOPS + op) * STAGES * STG_BYTES + (bnRow * 12 + bkh * 4) * 4;

    const int NC = K / 16;
    const size_t aRow = (size_t)(m0 + lrow) * lda + lkh * 8;
    const size_t bRow = (size_t)(n0 + lrow) * ldb + lkh * 8;

    #pragma unroll
    for (int s = 0; s < STAGES - 1; s++) {
        #pragma unroll
        for (int op = 0; op < NOPS; op++) {
            CP_ASYNC16(aDst0[op] + s * STG_BYTES, aps[op] + aRow + s * 16);
            CP_ASYNC16(bDst0[op] + s * STG_BYTES, bps[op] + bRow + s * 16);
        }
        CP_COMMIT();
    }

    int stage = 0;
    int pstage = STAGES - 1;
    for (int c = 0; c < NC; c++) {
        cp_wait<STAGES - 2>();
        __syncthreads();
        if (c + STAGES - 1 < NC) {
            int kk = (c + STAGES - 1) * 16;
            #pragma unroll
            for (int op = 0; op < NOPS; op++) {
                CP_ASYNC16(aDst0[op] + pstage * STG_BYTES, aps[op] + aRow + kk);
                CP_ASYNC16(bDst0[op] + pstage * STG_BYTES, bps[op] + bRow + kk);
            }
        }
        CP_COMMIT();

        const int so = stage * STG_BYTES;
        uint32_t a[NOPS][2][4];
        #pragma unroll
        for (int op = 0; op < NOPS; op++) {
            ldm_x4(a[op][0], aF0[op][0] + so);
            ldm_x4(a[op][1], aF0[op][1] + so);
        }
        #pragma unroll
        for (int g = 0; g < 4; g++) {
            uint32_t bh[4], bl[4];
            ldm_x4(bh, bF0[0] + so + g * 16 * 48);
            if (X3) ldm_x4(bl, bF0[1] + so + g * 16 * 48);
            #pragma unroll
            for (int h = 0; h < 2; h++) {
                int ni = g * 2 + h;
                mma16(acc[0][ni], a[0][0], bh[2 * h], bh[2 * h + 1]);
                mma16(acc[1][ni], a[0][1], bh[2 * h], bh[2 * h + 1]);
                if (X3) {
                    mma16(acc[0][ni], a[0][0], bl[2 * h], bl[2 * h + 1]);
                    mma16(acc[1][ni], a[0][1], bl[2 * h], bl[2 * h + 1]);
                    mma16(acc[0][ni], a[1][0], bh[2 * h], bh[2 * h + 1]);
                    mma16(acc[1][ni], a[1][1], bh[2 * h], bh[2 * h + 1]);
                }
            }
        }
        stage = (stage + 1 == STAGES) ? 0 : stage + 1;
        pstage = (pstage + 1 == STAGES) ? 0 : pstage + 1;
    }

    // epilogue
    #pragma unroll
    for (int mi = 0; mi < 2; mi++) {
        int r0o = m0 + wm + mi * 16 + lq;
        #pragma unroll
        for (int ni = 0; ni < 8; ni++) {
            int c = n0 + wn + ni * 8 + lr * 2;
            float bv0 = HASBIAS ? bias[c] : 0.f;
            float bv1 = HASBIAS ? bias[c + 1] : 0.f;
            float v0x = acc[mi][ni][0] + bv0, v0y = acc[mi][ni][1] + bv1;
            float v1x = acc[mi][ni][2] + bv0, v1y = acc[mi][ni][3] + bv1;
            if (RELU) {
                v0x = fmaxf(v0x, 0.f); v0y = fmaxf(v0y, 0.f);
                v1x = fmaxf(v1x, 0.f); v1y = fmaxf(v1y, 0.f);
            }
            if (EPI == 0) {
                *reinterpret_cast<float2*>(&C[(size_t)r0o * ldc + c]) = {v0x, v0y};
                *reinterpret_cast<float2*>(&C[(size_t)(r0o + 8) * ldc + c]) = {v1x, v1y};
            } else {
                uint32_t* Ch = reinterpret_cast<uint32_t*>(C);
                uint32_t* Cl = reinterpret_cast<uint32_t*>(C2);
                int p = c >> 1;
                uint32_t h0, l0, h1, l1;
                hilo2(v0x, v0y, h0, l0);
                hilo2(v1x, v1y, h1, l1);
                Ch[(size_t)r0o * ldc + p] = h0;       Cl[(size_t)r0o * ldc + p] = l0;
                Ch[(size_t)(r0o + 8) * ldc + p] = h1; Cl[(size_t)(r0o + 8) * ldc + p] = l1;
            }
        }
    }
}

// smem sizes
#define SMEM_X3  (3 * 2 * 2 * STG_BYTES)   // STAGES=3, NOPS=2 -> 73728
#define SMEM_1X  (4 * 1 * 2 * STG_BYTES)   // STAGES=4, NOPS=1 -> 49152

// ---------------- reduce MGT split-K partials + fp16 copy --------------------
__global__ void mgt_reduce_kernel() {
    size_t p = (size_t)blockIdx.x * 256 + threadIdx.x;
    size_t i0 = p * 2;
    float s0 = 0.f, s1 = 0.f;
    #pragma unroll
    for (int q = 0; q < NSPLIT; q++) {
        s0 += g_part[(size_t)q * (1024 * CH) + i0];
        s1 += g_part[(size_t)q * (1024 * CH) + i0 + 1];
    }
    g_MGT[i0] = s0;
    g_MGT[i0 + 1] = s1;
    g_MGThi[p] = pack2(s0, s1);
}

// ====== multistage fp16 1x HMMA: s write + Σq for u-half (STAGES=4) =========
__global__ void __launch_bounds__(256)
su16q_kernel(const __half* __restrict__ Ah, const __half* __restrict__ Bh,
             const float* __restrict__ bias, float* __restrict__ S) {
    constexpr int STAGES = 4;
    extern __shared__ uint32_t sm[];
    __shared__ double qred[8];
    const uint32_t smBase = cvta_smem(sm);
    const int tid  = threadIdx.x;
    const int lane = tid & 31;
    const int wid  = tid >> 5;
    const int n0 = blockIdx.x * 128;
    const int m0 = blockIdx.y * 128;
    const int wm = (wid & 3) * 32;
    const int wn = (wid >> 2) * 64;
    const int lq = lane >> 2;
    const int lr = lane & 3;

    float acc[2][8][4];
    #pragma unroll
    for (int mi = 0; mi < 2; mi++)
        #pragma unroll
        for (int ni = 0; ni < 8; ni++)
            #pragma unroll
            for (int j = 0; j < 4; j++) acc[mi][ni][j] = 0.f;

    const int lrow = tid >> 1;
    const int lkh  = tid & 1;
    uint32_t aDst0 = smBase + (lrow * 12 + lkh * 4) * 4;
    uint32_t bDst0 = smBase + STAGES * STG_BYTES + (lrow * 12 + lkh * 4) * 4;
    const int amRow = wm + (lane & 15);
    const int akh   = lane >> 4;
    uint32_t aF0[2];
    aF0[0] = smBase + (amRow * 12 + akh * 4) * 4;
    aF0[1] = aF0[0] + 16 * 48;
    const int bnRow = wn + (lane & 7) + ((lane & 16) >> 1);
    const int bkh   = (lane >> 3) & 1;
    uint32_t bF0 = smBase + STAGES * STG_BYTES + (bnRow * 12 + bkh * 4) * 4;

    const size_t aRow = (size_t)(m0 + lrow) * 1024 + lkh * 8;
    const size_t bRow = (size_t)(n0 + lrow) * 512 + lkh * 8;
    const int NC = 32;

    #pragma unroll
    for (int s = 0; s < STAGES - 1; s++) {
        CP_ASYNC16(aDst0 + s * STG_BYTES, Ah + aRow + s * 16);
        CP_ASYNC16(bDst0 + s * STG_BYTES, Bh + bRow + s * 16);
        CP_COMMIT();
    }

    int stage = 0, pstage = STAGES - 1;
    for (int c = 0; c < NC; c++) {
        cp_wait<STAGES - 2>();
        __syncthreads();
        if (c + STAGES - 1 < NC) {
            int kk = (c + STAGES - 1) * 16;
            CP_ASYNC16(aDst0 + pstage * STG_BYTES, Ah + aRow + kk);
            CP_ASYNC16(bDst0 + pstage * STG_BYTES, Bh + bRow + kk);
        }
        CP_COMMIT();

        const int so = stage * STG_BYTES;
        uint32_t a[2][4];
        ldm_x4(a[0], aF0[0] + so);
        ldm_x4(a[1], aF0[1] + so);
        #pragma unroll
        for (int g = 0; g < 4; g++) {
            uint32_t bh[4];
            ldm_x4(bh, bF0 + so + g * 16 * 48);
            #pragma unroll
            for (int h = 0; h < 2; h++) {
                int ni = g * 2 + h;
                mma16(acc[0][ni], a[0], bh[2 * h], bh[2 * h + 1]);
                mma16(acc[1][ni], a[1], bh[2 * h], bh[2 * h + 1]);
            }
        }
        stage = (stage + 1 == STAGES) ? 0 : stage + 1;
        pstage = (pstage + 1 == STAGES) ? 0 : pstage + 1;
    }

    if (n0 < 512) {
        #pragma unroll
        for (int mi = 0; mi < 2; mi++) {
            int r0o = m0 + wm + mi * 16 + lq;
            #pragma unroll
            for (int ni = 0; ni < 8; ni++) {
                int c = n0 + wn + ni * 8 + lr * 2;
                float bv0 = bias[c], bv1 = bias[c + 1];
                *reinterpret_cast<float2*>(&S[(size_t)r0o * 512 + c]) =
                    {acc[mi][ni][0] + bv0, acc[mi][ni][1] + bv1};
                *reinterpret_cast<float2*>(&S[(size_t)(r0o + 8) * 512 + c]) =
                    {acc[mi][ni][2] + bv0, acc[mi][ni][3] + bv1};
            }
        }
    } else {
        double qp = 0.0;
        #pragma unroll
        for (int mi = 0; mi < 2; mi++) {
            int r0o = m0 + wm + mi * 16 + lq;
            #pragma unroll
            for (int ni = 0; ni < 8; ni++) {
                int cg = (n0 - 512) + wn + ni * 8 + lr * 2;
                int p = cg >> 1;
                float bv0 = bias[512 + cg], bv1 = bias[512 + cg + 1];
                #pragma unroll
                for (int rr = 0; rr < 2; rr++) {
                    int r = r0o + rr * 8;
                    uint32_t uh = g_h1hi[(size_t)r * 512 + p];
                    uint32_t ul = g_h1lo[(size_t)r * 512 + p];
                    float2 fh = __half22float2(*reinterpret_cast<__half2*>(&uh));
                    float2 fl = __half22float2(*reinterpret_cast<__half2*>(&ul));
                    qp += (double)((acc[mi][ni][rr * 2] + bv0) * (fh.x + fl.x))
                        + (double)((acc[mi][ni][rr * 2 + 1] + bv1) * (fh.y + fl.y));
                }
            }
        }
        #pragma unroll
        for (int o = 16; o; o >>= 1) qp += __shfl_xor_sync(0xFFFFFFFFu, qp, o);
        if (lane == 0) qred[wid] = qp;
        __syncthreads();
        if (tid == 0) {
            double t = 0.0;
            #pragma unroll
            for (int i = 0; i < 8; i++) t += qred[i];
            atomicAdd(&g_sum, t);
        }
    }
}

// ---------- per-row top-2 argmin + flags + v1 accumulation --------
__global__ void argmin_kernel(float* __restrict__ out_ind_f) {
    __shared__ double s_v[8];
    int warp = threadIdx.x >> 5;
    int lane = threadIdx.x & 31;
    int b = blockIdx.x * 8 + warp;

    const float* su = g_S + (size_t)b * 512;

    float v1 = FLT_MAX, v2 = FLT_MAX;
    int   k1 = -1, k2 = -1;
    for (int k = lane; k < NUM_EMB; k += 32) {
        float v = g_e2[k] - 2.f * su[k];
        if (v < v1 || (v == v1 && k < k1)) { v2 = v1; k2 = k1; v1 = v; k1 = k; }
        else if (v < v2 || (v == v2 && k < k2)) { v2 = v; k2 = k; }
    }
    #pragma unroll
    for (int o = 16; o; o >>= 1) {
        float ov1 = __shfl_xor_sync(0xFFFFFFFFu, v1, o);
        int   ok1 = __shfl_xor_sync(0xFFFFFFFFu, k1, o);
        float ov2 = __shfl_xor_sync(0xFFFFFFFFu, v2, o);
        int   ok2 = __shfl_xor_sync(0xFFFFFFFFu, k2, o);
        if (!(ov1 == v1 && ok1 == k1)) {
            if (ov1 < v1 || (ov1 == v1 && ok1 < k1)) { v2 = v1; k2 = k1; v1 = ov1; k1 = ok1; }
            else if (ov1 < v2 || (ov1 == v2 && ok1 < k2)) { v2 = ov1; k2 = ok1; }
        }
        if (!(ov2 == v1 && ok2 == k1)) {
            if (ov2 < v1 || (ov2 == v1 && ok2 < k1)) { v2 = v1; k2 = k1; v1 = ov2; k1 = ok2; }
            else if (ov2 < v2 || (ov2 == v2 && ok2 < k2)) { v2 = ov2; k2 = ok2; }
        }
    }
    if (lane == 0) {
        g_ind[b] = k1;
        out_ind_f[b] = (float)k1;
        s_v[warp] = (double)v1;
        if (v2 - v1 < MARGIN && k2 >= 0) {
            int idx = atomicAdd(&g_nflag, 1);
            if (idx < MAXFLAG) {
                g_fb[idx] = b; g_fk1[idx] = k1; g_fk2[idx] = k2;
            }
        }
    }
    __syncthreads();
    if (threadIdx.x == 0) {
        double t = 0.0;
        #pragma unroll
        for (int i = 0; i < 8; i++) t += s_v[i];
        atomicAdd(&g_sum, t);
    }
}

// ----- refinement via M (fp64): one warp per flagged row -----
__global__ void refine_kernel(float* __restrict__ out_ind_f) {
    int nf = g_nflag; if (nf > MAXFLAG) nf = MAXFLAG;
    int f = (blockIdx.x * 256 + threadIdx.x) >> 5;
    int lane = threadIdx.x & 31;
    if (f >= nf) return;
    int b = g_fb[f];
    int k1 = g_fk1[f], k2 = g_fk2[f];
    const float* m1 = g_MGT + (size_t)k1 * CH;
    const float* m2 = g_MGT + (size_t)k2 * CH;
    double s = 0.0;
    for (int p = lane; p < 256; p += 32) {
        uint32_t uh = g_h1hi[(size_t)b * 512 + p];
        uint32_t ul = g_h1lo[(size_t)b * 512 + p];
        float2 fh = __half22float2(*reinterpret_cast<__half2*>(&uh));
        float2 fl = __half22float2(*reinterpret_cast<__half2*>(&ul));
        double h0 = (double)fh.x + (double)fl.x;
        double h1 = (double)fh.y + (double)fl.y;
        int j = p * 2;
        s += h0 * ((double)m2[j] - (double)m1[j]);
        s += h1 * ((double)m2[j + 1] - (double)m1[j + 1]);
    }
    #pragma unroll
    for (int o = 16; o; o >>= 1) s += __shfl_xor_sync(0xFFFFFFFFu, s, o);
    if (lane == 0) {
        double delta = (g_e2d[k2] - g_e2d[k1]) - 2.0 * (s + (g_cd[k2] - g_cd[k1]));
        if (delta < 0.0 || (delta == 0.0 && k2 < k1)) {
            g_ind[b] = k2;
            out_ind_f[b] = (float)k2;
        }
    }
}

// ---------------- expert histogram / scan / scatter ----------------
__global__ void hist_kernel() {
    __shared__ int h[NUM_EMB];
    int t = threadIdx.x;
    h[t] = 0; h[t + 256] = 0;
    __syncthreads();
    int i0 = blockIdx.x * 2048;
    for (int i = t; i < 2048; i += 256)
        atomicAdd(&h[g_ind[i0 + i]], 1);
    __syncthreads();
    if (h[t]) atomicAdd(&g_counts[t], h[t]);
    if (h[t + 256]) atomicAdd(&g_counts[t + 256], h[t + 256]);
}

__global__ void scan_kernel() {
    __shared__ int tmp[NUM_EMB];
    int t = threadIdx.x;
    int v0 = g_counts[t];
    tmp[t] = v0;
    __syncthreads();
    for (int off = 1; off < NUM_EMB; off <<= 1) {
        int v = (t >= off) ? tmp[t - off] : 0;
        __syncthreads();
        tmp[t] += v;
        __syncthreads();
    }
    g_woff[t] = tmp[t] - v0;   // exclusive prefix
}

__global__ void scatter_kernel() {
    int b = blockIdx.x * 256 + threadIdx.x;
    int k = g_ind[b];
    int pos = atomicAdd(&g_woff[k], 1);
    g_order[pos] = b;
}

// ---------------- per-sample expert MLP decode (expert-sorted) ---------------
__global__ void decoder_kernel(const float* __restrict__ W1, const float* __restrict__ b1,
                               const float* __restrict__ W2, const float* __restrict__ b2,
                               float* __restrict__ out) {
    __shared__ float exs[8][64];
    __shared__ float hs [8][64];
    int warp = threadIdx.x >> 5;
    int lane = threadIdx.x & 31;
    int b = g_order[blockIdx.x * 8 + warp];

    exs[warp][lane]      = g_expad[(size_t)b * 128 + lane];
    exs[warp][lane + 32] = g_expad[(size_t)b * 128 + lane + 32];
    __syncwarp();

    int k = g_ind[b];
    const float* w1 = W1 + (size_t)k * 64 * 64;
    float h0 = b1[k * 64 + lane];
    float h1 = b1[k * 64 + lane + 32];
    #pragma unroll 8
    for (int i = 0; i < 64; i++) {
        float xi = exs[warp][i];
        h0 += xi * w1[i * 64 + lane];
        h1 += xi * w1[i * 64 + lane + 32];
    }
    hs[warp][lane]      = fmaxf(h0, 0.f);
    hs[warp][lane + 32] = fmaxf(h1, 0.f);
    __syncwarp();

    const float* w2 = W2 + (size_t)k * 64 * 32;
    float o = b2[k * 32 + lane];
    #pragma unroll 8
    for (int i = 0; i < 64; i++)
        o += hs[warp][i] * w2[i * 32 + lane];
    out[(size_t)b * 32 + lane] = o;
}

// ---------------- finalize: diff + perplexity (uses g_counts) ----------------
__global__ void finalize_kernel(float* __restrict__ out) {
    __shared__ float red[512];
    int k = threadIdx.x;
    float p = (float)g_counts[k] / (float)BATCH;
    red[k] = -p * logf(p + 1e-10f);
    __syncthreads();
    for (int s = 256; s; s >>= 1) {
        if (k < s) red[k] += red[k + s];
        __syncthreads();
    }
    if (k == 0) {
        double total = g_sum + (double)BATCH * (double)g_beta;
        out[OUT_DIFF] = (float)(total / ((double)BATCH * (double)EMBED_D));
        out[OUT_PERP] = expf(red[0]);
    }
}

// ---------------- launch ----------------
extern "C" void kernel_launch(void* const* d_in, const int* in_sizes, int n_in,
                              void* d_out, int out_size) {
    const float* x     = (const float*)d_in[0];
    const float* Wf1   = (const float*)d_in[1];
    const float* bf1   = (const float*)d_in[2];
    const float* Wf2   = (const float*)d_in[3];
    const float* bf2   = (const float*)d_in[4];
    const float* Wx1   = (const float*)d_in[5];
    const float* bx1   = (const float*)d_in[6];
    const float* Wx2   = (const float*)d_in[7];
    const float* bx2   = (const float*)d_in[8];
    const float* embed = (const float*)d_in[9];
    const float* W1    = (const float*)d_in[10];
    const float* b1    = (const float*)d_in[11];
    const float* W2    = (const float*)d_in[12];
    const float* b2    = (const float*)d_in[13];
    float* out = (float*)d_out;

    void *p_h1hi, *p_h1lo, *p_S, *p_expad, *p_MGThi, *p_bias2, *p_part,
         *p_BcatTh, *p_BcatTl, *p_Wf2h, *p_Wf2l, *p_xh, *p_xl,
         *p_B1h, *p_B1l, *p_Wx2h, *p_Wx2l, *p_biascat1, *p_bx2pad;
    cudaGetSymbolAddress(&p_h1hi, g_h1hi);
    cudaGetSymbolAddress(&p_h1lo, g_h1lo);
    cudaGetSymbolAddress(&p_S,    g_S);
    cudaGetSymbolAddress(&p_expad,g_expad);
    cudaGetSymbolAddress(&p_MGThi,g_MGThi);
    cudaGetSymbolAddress(&p_bias2,g_bias2);
    cudaGetSymbolAddress(&p_part, g_part);
    cudaGetSymbolAddress(&p_BcatTh, g_BcatTh);
    cudaGetSymbolAddress(&p_BcatTl, g_BcatTl);
    cudaGetSymbolAddress(&p_Wf2h, g_Wf2h);
    cudaGetSymbolAddress(&p_Wf2l, g_Wf2l);
    cudaGetSymbolAddress(&p_xh,   g_xh);
    cudaGetSymbolAddress(&p_xl,   g_xl);
    cudaGetSymbolAddress(&p_B1h,  g_B1h);
    cudaGetSymbolAddress(&p_B1l,  g_B1l);
    cudaGetSymbolAddress(&p_Wx2h, g_Wx2h);
    cudaGetSymbolAddress(&p_Wx2l, g_Wx2l);
    cudaGetSymbolAddress(&p_biascat1, g_biascat1);
    cudaGetSymbolAddress(&p_bx2pad,   g_bx2pad);

    cudaFuncSetAttribute((const void*)hgemm<true, 3, 0, false, false, true>,
                         cudaFuncAttributeMaxDynamicSharedMemorySize, SMEM_X3);
    cudaFuncSetAttribute((const void*)hgemm<false, 4, 0, false, false, true>,
                         cudaFuncAttributeMaxDynamicSharedMemorySize, SMEM_1X);
    cudaFuncSetAttribute((const void*)hgemm<true, 3, 1, true, true, false>,
                         cudaFuncAttributeMaxDynamicSharedMemorySize, SMEM_X3);
    cudaFuncSetAttribute((const void*)hgemm<true, 3, 0, true, false, false>,
                         cudaFuncAttributeMaxDynamicSharedMemorySize, SMEM_X3);
    cudaFuncSetAttribute((const void*)su16q_kernel,
                         cudaFuncAttributeMaxDynamicSharedMemorySize, SMEM_1X);

    // side stream + events (created per call; never destroyed; graph-capturable)
    cudaStream_t s1;
    cudaStreamCreateWithFlags(&s1, cudaStreamNonBlocking);
    cudaEvent_t evA, evB, evC;
    cudaEventCreateWithFlags(&evA, cudaEventDisableTiming);
    cudaEventCreateWithFlags(&evB, cudaEventDisableTiming);
    cudaEventCreateWithFlags(&evC, cudaEventDisableTiming);

    // common prep on default stream
    prep1_kernel<<<J_TOT, 256>>>(embed, Wf2, Wf1, Wx1, bf1, bx1, Wx2, bx2);
    cudaEventRecord(evA, 0);
    cudaStreamWaitEvent(s1, evA, 0);

    // ---- chain B on s1: xsplit -> h1cat -> (evB) -> ex -> (evC) ----
    xsplit_kernel<<<BATCH * IN_C / 4 / 256, 256, 0, s1>>>(x);
    hgemm<true, 3, 1, true, true, false><<<dim3(8, 128), 256, SMEM_X3, s1>>>(
        (const __half*)p_xh, (const __half*)p_xl,
        (const __half*)p_B1h, (const __half*)p_B1l,
        (const float*)p_biascat1, (float*)p_h1hi, (float*)p_h1lo,
        BATCH, 1024, IN_C, IN_C, IN_C, 512, 0);
    cudaEventRecord(evB, s1);
    hgemm<true, 3, 0, true, false, false><<<dim3(1, 128), 256, SMEM_X3, s1>>>(
        (const __half*)p_h1hi + 512, (const __half*)p_h1lo + 512,
        (const __half*)p_Wx2h, (const __half*)p_Wx2l,
        (const float*)p_bx2pad, (float*)p_expad, nullptr,
        BATCH, 128, CH, 1024, CH, 128, 0);
    cudaEventRecord(evC, s1);

    // ---- chain A on default stream: MG + scalar prep ----
    hgemm<true, 3, 0, false, false, true><<<dim3(4, 4, NSPLIT), 256, SMEM_X3>>>(
        (const __half*)p_BcatTh, (const __half*)p_BcatTl,
        (const __half*)p_Wf2h, (const __half*)p_Wf2l,
        nullptr, (float*)p_part, nullptr,
        1024, CH, EMBED_D, EMBED_D, EMBED_D, CH, 0);
    hgemm<false, 4, 0, false, false, true><<<dim3(4, 4, NSPLIT), 256, SMEM_1X>>>(
        (const __half*)p_BcatTh, nullptr,
        (const __half*)p_Wf2h, nullptr,
        nullptr, (float*)p_part, nullptr,
        1024, CH, EMBED_D, EMBED_D, EMBED_D, CH, 512);
    mgt_reduce_kernel<<<1024 * 256 / 256, 256>>>();
    prep2_kernel<<<NCHUNKD + 160 + 1, 512>>>(embed, Wf2, bf2);
    prep3_kernel<<<1, 1024>>>();

    // join: su16q needs h1cat
    cudaStreamWaitEvent(0, evB, 0);
    su16q_kernel<<<dim3(8, 128), 256, SMEM_1X>>>(
        (const __half*)p_h1hi, (const __half*)p_MGThi,
        (const float*)p_bias2, (float*)p_S);

    argmin_kernel<<<BATCH / 8, 256>>>(out + OUT_IND);
    refine_kernel<<<MAXFLAG / 8, 256>>>(out + OUT_IND);

    // expert-sort for decoder locality
    hist_kernel<<<BATCH / 2048, 256>>>();
    scan_kernel<<<1, 512>>>();
    scatter_kernel<<<BATCH / 256, 256>>>();

    // decoder needs ex (chain B)
    cudaStreamWaitEvent(0, evC, 0);
    decoder_kernel<<<BATCH / 8, 256>>>(W1, b1, W2, b2, out);
    finalize_kernel<<<1, 512>>>(out);
}

// round 16
// speedup vs baseline: 1.2102x; 1.2102x over previous
#include <cuda_runtime.h>
#include <cuda_fp16.h>
#include <math.h>
#include <float.h>
#include <stdint.h>

// Problem dims
#define BATCH    16384
#define IN_C     128
#define CH       512
#define EMBED_D  6240
#define NUM_EMB  512
#define DEC_IN   64
#define DATA_Y   32

// Output layout (float32): dec[B*32], diff[1], embed_ind[B], perplexity[1]
#define OUT_DIFF  (BATCH * DATA_Y)
#define OUT_IND   (OUT_DIFF + 1)
#define OUT_PERP  (OUT_IND + BATCH)

#define MAXFLAG 16384
#define MARGIN  2.0f

#define NSPLIT  26
#define KCHUNK  240           // 26 * 240 = 6240
#define NCHUNKD 195
#define DCHUNK  32
#define NCHUNKG 5
#define GCHUNK  1248

// ---------------- scratch (device globals) ----------------
__device__ __align__(16) uint32_t g_h1hi[BATCH * 512];
__device__ __align__(16) uint32_t g_h1lo[BATCH * 512];
__device__ __align__(16) float  g_S [BATCH * 512];
__device__ __align__(16) float  g_expad[BATCH * 128];
__device__ __align__(16) float  g_part[NSPLIT * 1024 * CH];
__device__ __align__(16) float  g_MGT [1024 * CH];
__device__ __align__(16) uint32_t g_MGThi[1024 * 256];
__device__ __align__(16) __half g_BcatTh[1024 * EMBED_D];
__device__ __align__(16) __half g_BcatTl[1024 * EMBED_D];
__device__ __align__(16) __half g_Wf2h[CH * EMBED_D];
__device__ __align__(16) __half g_Wf2l[CH * EMBED_D];
__device__ __align__(16) __half g_xh[BATCH * IN_C];
__device__ __align__(16) __half g_xl[BATCH * IN_C];
__device__ __align__(16) __half g_B1h[1024 * IN_C];
__device__ __align__(16) __half g_B1l[1024 * IN_C];
__device__ __align__(16) __half g_Wx2h[128 * CH];
__device__ __align__(16) __half g_Wx2l[128 * CH];
__device__ float  g_bx2pad[128];
__device__ float  g_biascat1[1024];
__device__ float  g_bias2[1024];
__device__ float  g_e2[NUM_EMB];
__device__ double g_e2d[NUM_EMB];
__device__ double g_cd[NUM_EMB];
__device__ float  g_beta;
__device__ double g_sum;
__device__ int    g_ind[BATCH];
__device__ double g_pc [NCHUNKD * NUM_EMB];
__device__ double g_pe2[NCHUNKD * NUM_EMB];
__device__ double g_pg [NCHUNKG * CH];
__device__ int    g_nflag;
__device__ int    g_fb [MAXFLAG];
__device__ int    g_fk1[MAXFLAG];
__device__ int    g_fk2[MAXFLAG];

// ------------------------ helpers ------------------------
__device__ __forceinline__ uint32_t pack2(float a, float b) {
    __half2 h = __floats2half2_rn(a, b);
    return *reinterpret_cast<uint32_t*>(&h);
}
__device__ __forceinline__ void hilo2(float a, float b, uint32_t& hi, uint32_t& lo) {
    __half ha = __float2half_rn(a), hb = __float2half_rn(b);
    float la = a - __half2float(ha);
    float lb = b - __half2float(hb);
    __half2 h = __halves2half2(ha, hb);
    hi = *reinterpret_cast<uint32_t*>(&h);
    lo = pack2(la, lb);
}
__device__ __forceinline__ void mma16(float* c, const uint32_t* a,
                                      uint32_t b0, uint32_t b1) {
    asm volatile("mma.sync.aligned.m16n8k16.row.col.f32.f16.f16.f32 "
        "{%0,%1,%2,%3}, {%4,%5,%6,%7}, {%8,%9}, {%0,%1,%2,%3};"
        : "+f"(c[0]), "+f"(c[1]), "+f"(c[2]), "+f"(c[3])
        : "r"(a[0]), "r"(a[1]), "r"(a[2]), "r"(a[3]), "r"(b0), "r"(b1));
}
__device__ __forceinline__ uint32_t cvta_smem(const void* p) {
    uint32_t a;
    asm("{ .reg .u64 t; cvta.to.shared.u64 t, %1; cvt.u32.u64 %0, t; }"
        : "=r"(a) : "l"(p));
    return a;
}
#define CP_ASYNC16(dst, src) \
    asm volatile("cp.async.ca.shared.global [%0], [%1], 16;" \
                 :: "r"(dst), "l"(src) : "memory")
#define CP_COMMIT() asm volatile("cp.async.commit_group;" ::: "memory")
template<int N>
__device__ __forceinline__ void cp_wait() {
    asm volatile("cp.async.wait_group %0;" :: "n"(N) : "memory");
}
__device__ __forceinline__ void ldm_x4(uint32_t* r, uint32_t addr) {
    asm volatile("ldmatrix.sync.aligned.m8n8.x4.shared.b16 {%0,%1,%2,%3}, [%4];"
        : "=r"(r[0]), "=r"(r[1]), "=r"(r[2]), "=r"(r[3]) : "r"(addr));
}

// stage block: 128 rows x 12 u32 (stride 12 => conflict-free ldmatrix) = 6144 B
#define STG_BYTES 6144

// ============================ mega-prep =====================================
#define J_EMBT   3120
#define J_WF2    (J_EMBT + 3120)
#define J_B1T    (J_WF2 + 128)
#define J_WX2    (J_B1T + 64)
#define J_TOT    (J_WX2 + 1)
__global__ void prep1_kernel(const float* __restrict__ embed,
                             const float* __restrict__ Wf2,
                             const float* __restrict__ Wf1,
                             const float* __restrict__ Wx1,
                             const float* __restrict__ bf1,
                             const float* __restrict__ bx1,
                             const float* __restrict__ Wx2,
                             const float* __restrict__ bx2) {
    __shared__ float t[32][33];
    const int bi = blockIdx.x;
    const int tid = threadIdx.x;
    const int tx = tid & 31, ty = tid >> 5;

    if (bi < J_EMBT) {
        int d0 = (bi % 195) * 32;
        int k0 = (bi / 195) * 32;
        #pragma unroll
        for (int r = 0; r < 32; r += 8)
            t[ty + r][tx] = embed[(size_t)(d0 + ty + r) * 512 + k0 + tx];
        __syncthreads();
        #pragma unroll
        for (int r = 0; r < 32; r += 8) {
            float v = t[tx][ty + r];
            __half h = __float2half_rn(v);
            size_t o = (size_t)(k0 + ty + r) * EMBED_D + d0 + tx;
            g_BcatTh[o] = h;
            g_BcatTl[o] = __float2half_rn(v - __half2float(h));
        }
    } else if (bi < J_WF2) {
        size_t i = (size_t)(bi - J_EMBT) * 256 + tid;
        float4 v = reinterpret_cast<const float4*>(Wf2)[i];
        uint32_t h0, l0, h1, l1;
        hilo2(v.x, v.y, h0, l0);
        hilo2(v.z, v.w, h1, l1);
        uint2 uh = {h0, h1}, ul = {l0, l1};
        reinterpret_cast<uint2*>(g_Wf2h)[i] = uh;
        reinterpret_cast<uint2*>(g_Wf2l)[i] = ul;
        reinterpret_cast<uint2*>(g_BcatTh)[798720 + i] = uh;
        reinterpret_cast<uint2*>(g_BcatTl)[798720 + i] = ul;
    } else if (bi < J_B1T) {
        int b2 = bi - J_WF2;
        int n0 = (b2 & 31) * 32;
        int k0 = (b2 >> 5) * 32;
        #pragma unroll
        for (int r = 0; r < 32; r += 8) {
            int n = n0 + tx;
            t[ty + r][tx] = (n < 512)
                ? Wf1[(size_t)(k0 + ty + r) * 512 + n]
                : Wx1[(size_t)(k0 + ty + r) * 512 + n - 512];
        }
        __syncthreads();
        #pragma unroll
        for (int r = 0; r < 32; r += 8) {
            float v = t[tx][ty + r];
            __half h = __float2half_rn(v);
            size_t o = (size_t)(n0 + ty + r) * IN_C + k0 + tx;
            g_B1h[o] = h;
            g_B1l[o] = __float2half_rn(v - __half2float(h));
        }
    } else if (bi < J_WX2) {
        int base = (bi - J_B1T) * 1024 + tid * 4;
        float vv[4];
        #pragma unroll
        for (int j = 0; j < 4; j++) {
            int idx = base + j;
            int n = idx >> 9, k = idx & 511;
            vv[j] = (n < 64) ? Wx2[(size_t)k * 64 + n] : 0.f;
        }
        uint32_t h0, l0, h1, l1;
        hilo2(vv[0], vv[1], h0, l0);
        hilo2(vv[2], vv[3], h1, l1);
        reinterpret_cast<uint2*>(g_Wx2h)[base >> 2] = {h0, h1};
        reinterpret_cast<uint2*>(g_Wx2l)[base >> 2] = {l0, l1};
        if (bi == J_B1T && tid < 128)
            g_bx2pad[tid] = (tid < 64) ? bx2[tid] : 0.f;
    } else {
        #pragma unroll
        for (int j = 0; j < 4; j++) {
            int k = tid + j * 256;
            g_biascat1[k] = (k < 512) ? bf1[k] : bx1[k - 512];
        }
        if (tid == 0) { g_sum = 0.0; g_nflag = 0; }
    }
}

__global__ void xsplit_kernel(const float* __restrict__ x) {
    size_t i = (size_t)blockIdx.x * 256 + threadIdx.x;
    float4 v = reinterpret_cast<const float4*>(x)[i];
    uint32_t h0, l0, h1, l1;
    hilo2(v.x, v.y, h0, l0);
    hilo2(v.z, v.w, h1, l1);
    reinterpret_cast<uint2*>(g_xh)[i] = {h0, h1};
    reinterpret_cast<uint2*>(g_xl)[i] = {l0, l1};
}

// ---------------- prep2: vq partials + g partials + beta ---------------------
__global__ void prep2_kernel(const float* __restrict__ embed,
                             const float* __restrict__ Wf2,
                             const float* __restrict__ bf2) {
    const int bi = blockIdx.x;
    if (bi < NCHUNKD) {
        int k = threadIdx.x;
        int d0 = bi * DCHUNK;
        double cc = 0.0, ee = 0.0;
        for (int d = d0; d < d0 + DCHUNK; d++) {
            double e = (double)embed[(size_t)d * NUM_EMB + k];
            cc += (double)bf2[d] * e;
            ee += e * e;
        }
        g_pc [bi * NUM_EMB + k] = cc;
        g_pe2[bi * NUM_EMB + k] = ee;
    } else if (bi < NCHUNKD + 160) {
        int gw = (bi - NCHUNKD) * 16 + (threadIdx.x >> 5);
        int lane = threadIdx.x & 31;
        int i = gw % CH;
        int c = gw / CH;
        const float* w = Wf2 + (size_t)i * EMBED_D + c * GCHUNK;
        const float* b = bf2 + c * GCHUNK;
        double s = 0.0;
        #pragma unroll 4
        for (int t = lane; t < GCHUNK; t += 32)
            s += (double)w[t] * (double)b[t];
        #pragma unroll
        for (int o = 16; o; o >>= 1) s += __shfl_xor_sync(0xFFFFFFFFu, s, o);
        if (lane == 0) g_pg[c * CH + i] = s;
    } else {
        __shared__ double red[512];
        double s = 0.0;
        for (int d = threadIdx.x; d < EMBED_D; d += 512) { double v = bf2[d]; s += v * v; }
        red[threadIdx.x] = s;
        __syncthreads();
        for (int t = 256; t; t >>= 1) {
            if (threadIdx.x < t) red[threadIdx.x] += red[threadIdx.x + t];
            __syncthreads();
        }
        if (threadIdx.x == 0) g_beta = (float)red[0];
    }
}

__global__ void prep3_kernel() {
    int k = threadIdx.x;
    if (k < 512) {
        double cc = 0.0, ee = 0.0;
        for (int s = 0; s < NCHUNKD; s++) {
            cc += g_pc [s * NUM_EMB + k];
            ee += g_pe2[s * NUM_EMB + k];
        }
        g_bias2[k] = (float)cc;
        g_cd[k]  = cc;
        g_e2[k]  = (float)ee;
        g_e2d[k] = ee;
    } else {
        int i = k - 512;
        double s = 0.0;
        #pragma unroll
        for (int c = 0; c < NCHUNKG; c++) s += g_pg[c * CH + i];
        g_bias2[512 + i] = (float)(2.0 * s);
    }
}

// ====== multistage HMMA GEMM (cp.async ring + ldmatrix): C = op(A@Bt^T) ======
template<bool X3, int STAGES, int EPI, bool HASBIAS, bool RELU, bool SPLITK>
__global__ void __launch_bounds__(256)
hgemm(const __half* __restrict__ Ah, const __half* __restrict__ Al,
      const __half* __restrict__ Bh, const __half* __restrict__ Bl,
      const float* __restrict__ bias, float* __restrict__ C, float* __restrict__ C2,
      int M, int N, int K, int lda, int ldb, int ldc, int m_off) {
    constexpr int NOPS = X3 ? 2 : 1;
    extern __shared__ uint32_t sm[];
    const uint32_t smBase = cvta_smem(sm);
    const int tid  = threadIdx.x;
    const int lane = tid & 31;
    const int wid  = tid >> 5;
    const int n0 = blockIdx.x * 128;
    const int m0 = m_off + blockIdx.y * 128;
    if (SPLITK) {
        Ah += blockIdx.z * KCHUNK;  Bh += blockIdx.z * KCHUNK;
        if (X3) { Al += blockIdx.z * KCHUNK;  Bl += blockIdx.z * KCHUNK; }
        C  += (size_t)blockIdx.z * M * N;
        K = KCHUNK;
    }
    const int wm = (wid & 3) * 32;
    const int wn = (wid >> 2) * 64;
    const int lq = lane >> 2;
    const int lr = lane & 3;

    float acc[2][8][4];
    #pragma unroll
    for (int mi = 0; mi < 2; mi++)
        #pragma unroll
        for (int ni = 0; ni < 8; ni++)
            #pragma unroll
            for (int j = 0; j < 4; j++) acc[mi][ni][j] = 0.f;

    const int lrow = tid >> 1;
    const int lkh  = tid & 1;
    const __half* aps[2]; aps[0] = Ah; aps[1] = X3 ? Al : Ah;
    const __half* bps[2]; bps[0] = Bh; bps[1] = X3 ? Bl : Bh;

    uint32_t aDst0[NOPS], bDst0[NOPS];
    #pragma unroll
    for (int op = 0; op < NOPS; op++) {
        aDst0[op] = smBase + op * STAGES * STG_BYTES + (lrow * 12 + lkh * 4) * 4;
        bDst0[op] = smBase + (NOPS + op) * STAGES * STG_BYTES + (lrow * 12 + lkh * 4) * 4;
    }
    const int amRow = wm + (lane & 15);
    const int akh   = lane >> 4;
    uint32_t aF0[NOPS][2];
    #pragma unroll
    for (int op = 0; op < NOPS; op++) {
        aF0[op][0] = smBase + op * STAGES * STG_BYTES + (amRow * 12 + akh * 4) * 4;
        aF0[op][1] = aF0[op][0] + 16 * 48;
    }
    const int bnRow = wn + (lane & 7) + ((lane & 16) >> 1);
    const int bkh   = (lane >> 3) & 1;
    uint32_t bF0[NOPS];
    #pragma unroll
    for (int op = 0; op < NOPS; op++)
        bF0[op] = smBase + (NOPS + op) * STAGES * STG_BYTES + (bnRow * 12 + bkh * 4) * 4;

    const int NC = K / 16;
    const size_t aRow = (size_t)(m0 + lrow) * lda + lkh * 8;
    const size_t bRow = (size_t)(n0 + lrow) * ldb + lkh * 8;

    #pragma unroll
    for (int s = 0; s < STAGES - 1; s++) {
        #pragma unroll
        for (int op = 0; op < NOPS; op++) {
            CP_ASYNC16(aDst0[op] + s * STG_BYTES, aps[op] + aRow + s * 16);
            CP_ASYNC16(bDst0[op] + s * STG_BYTES, bps[op] + bRow + s * 16);
        }
        CP_COMMIT();
    }

    int stage = 0;
    int pstage = STAGES - 1;
    for (int c = 0; c < NC; c++) {
        cp_wait<STAGES - 2>();
        __syncthreads();
        if (c + STAGES - 1 < NC) {
            int kk = (c + STAGES - 1) * 16;
            #pragma unroll
            for (int op = 0; op < NOPS; op++) {
                CP_ASYNC16(aDst0[op] + pstage * STG_BYTES, aps[op] + aRow + kk);
                CP_ASYNC16(bDst0[op] + pstage * STG_BYTES, bps[op] + bRow + kk);
            }
        }
        CP_COMMIT();

        const int so = stage * STG_BYTES;
        uint32_t a[NOPS][2][4];
        #pragma unroll
        for (int op = 0; op < NOPS; op++) {
            ldm_x4(a[op][0], aF0[op][0] + so);
            ldm_x4(a[op][1], aF0[op][1] + so);
        }
        #pragma unroll
        for (int g = 0; g < 4; g++) {
            uint32_t bh[4], bl[4];
            ldm_x4(bh, bF0[0] + so + g * 16 * 48);
            if (X3) ldm_x4(bl, bF0[1] + so + g * 16 * 48);
            #pragma unroll
            for (int h = 0; h < 2; h++) {
                int ni = g * 2 + h;
                mma16(acc[0][ni], a[0][0], bh[2 * h], bh[2 * h + 1]);
                mma16(acc[1][ni], a[0][1], bh[2 * h], bh[2 * h + 1]);
                if (X3) {
                    mma16(acc[0][ni], a[0][0], bl[2 * h], bl[2 * h + 1]);
                    mma16(acc[1][ni], a[0][1], bl[2 * h], bl[2 * h + 1]);
                    mma16(acc[0][ni], a[1][0], bh[2 * h], bh[2 * h + 1]);
                    mma16(acc[1][ni], a[1][1], bh[2 * h], bh[2 * h + 1]);
                }
            }
        }
        stage = (stage + 1 == STAGES) ? 0 : stage + 1;
        pstage = (pstage + 1 == STAGES) ? 0 : pstage + 1;
    }

    // epilogue
    #pragma unroll
    for (int mi = 0; mi < 2; mi++) {
        int r0o = m0 + wm + mi * 16 + lq;
        #pragma unroll
        for (int ni = 0; ni < 8; ni++) {
            int c = n0 + wn + ni * 8 + lr * 2;
            float bv0 = HASBIAS ? bias[c] : 0.f;
            float bv1 = HASBIAS ? bias[c + 1] : 0.f;
            float v0x = acc[mi][ni][0] + bv0, v0y = acc[mi][ni][1] + bv1;
            float v1x = acc[mi][ni][2] + bv0, v1y = acc[mi][ni][3] + bv1;
            if (RELU) {
                v0x = fmaxf(v0x, 0.f); v0y = fmaxf(v0y, 0.f);
                v1x = fmaxf(v1x, 0.f); v1y = fmaxf(v1y, 0.f);
            }
            if (EPI == 0) {
                *reinterpret_cast<float2*>(&C[(size_t)r0o * ldc + c]) = {v0x, v0y};
                *reinterpret_cast<float2*>(&C[(size_t)(r0o + 8) * ldc + c]) = {v1x, v1y};
            } else {
                uint32_t* Ch = reinterpret_cast<uint32_t*>(C);
                uint32_t* Cl = reinterpret_cast<uint32_t*>(C2);
                int p = c >> 1;
                uint32_t h0, l0, h1, l1;
                hilo2(v0x, v0y, h0, l0);
                hilo2(v1x, v1y, h1, l1);
                Ch[(size_t)r0o * ldc + p] = h0;       Cl[(size_t)r0o * ldc + p] = l0;
                Ch[(size_t)(r0o + 8) * ldc + p] = h1; Cl[(size_t)(r0o + 8) * ldc + p] = l1;
            }
        }
    }
}

// smem sizes
#define SMEM_X3  (3 * 2 * 2 * STG_BYTES)   // STAGES=3, NOPS=2 -> 73728
#define SMEM_1X  (4 * 1 * 2 * STG_BYTES)   // STAGES=4, NOPS=1 -> 49152

// ---------------- reduce MGT split-K partials + fp16 copy --------------------
__global__ void mgt_reduce_kernel() {
    size_t p = (size_t)blockIdx.x * 256 + threadIdx.x;
    size_t i0 = p * 2;
    float s0 = 0.f, s1 = 0.f;
    #pragma unroll
    for (int q = 0; q < NSPLIT; q++) {
        s0 += g_part[(size_t)q * (1024 * CH) + i0];
        s1 += g_part[(size_t)q * (1024 * CH) + i0 + 1];
    }
    g_MGT[i0] = s0;
    g_MGT[i0 + 1] = s1;
    g_MGThi[p] = pack2(s0, s1);
}

// ====== multistage fp16 1x HMMA: s write + Σq for u-half (STAGES=4) =========
__global__ void __launch_bounds__(256)
su16q_kernel(const __half* __restrict__ Ah, const __half* __restrict__ Bh,
             const float* __restrict__ bias, float* __restrict__ S) {
    constexpr int STAGES = 4;
    extern __shared__ uint32_t sm[];
    __shared__ double qred[8];
    const uint32_t smBase = cvta_smem(sm);
    const int tid  = threadIdx.x;
    const int lane = tid & 31;
    const int wid  = tid >> 5;
    const int n0 = blockIdx.x * 128;
    const int m0 = blockIdx.y * 128;
    const int wm = (wid & 3) * 32;
    const int wn = (wid >> 2) * 64;
    const int lq = lane >> 2;
    const int lr = lane & 3;

    float acc[2][8][4];
    #pragma unroll
    for (int mi = 0; mi < 2; mi++)
        #pragma unroll
        for (int ni = 0; ni < 8; ni++)
            #pragma unroll
            for (int j = 0; j < 4; j++) acc[mi][ni][j] = 0.f;

    const int lrow = tid >> 1;
    const int lkh  = tid & 1;
    uint32_t aDst0 = smBase + (lrow * 12 + lkh * 4) * 4;
    uint32_t bDst0 = smBase + STAGES * STG_BYTES + (lrow * 12 + lkh * 4) * 4;
    const int amRow = wm + (lane & 15);
    const int akh   = lane >> 4;
    uint32_t aF0[2];
    aF0[0] = smBase + (amRow * 12 + akh * 4) * 4;
    aF0[1] = aF0[0] + 16 * 48;
    const int bnRow = wn + (lane & 7) + ((lane & 16) >> 1);
    const int bkh   = (lane >> 3) & 1;
    uint32_t bF0 = smBase + STAGES * STG_BYTES + (bnRow * 12 + bkh * 4) * 4;

    const size_t aRow = (size_t)(m0 + lrow) * 1024 + lkh * 8;
    const size_t bRow = (size_t)(n0 + lrow) * 512 + lkh * 8;
    const int NC = 32;

    #pragma unroll
    for (int s = 0; s < STAGES - 1; s++) {
        CP_ASYNC16(aDst0 + s * STG_BYTES, Ah + aRow + s * 16);
        CP_ASYNC16(bDst0 + s * STG_BYTES, Bh + bRow + s * 16);
        CP_COMMIT();
    }

    int stage = 0, pstage = STAGES - 1;
    for (int c = 0; c < NC; c++) {
        cp_wait<STAGES - 2>();
        __syncthreads();
        if (c + STAGES - 1 < NC) {
            int kk = (c + STAGES - 1) * 16;
            CP_ASYNC16(aDst0 + pstage * STG_BYTES, Ah + aRow + kk);
            CP_ASYNC16(bDst0 + pstage * STG_BYTES, Bh + bRow + kk);
        }
        CP_COMMIT();

        const int so = stage * STG_BYTES;
        uint32_t a[2][4];
        ldm_x4(a[0], aF0[0] + so);
        ldm_x4(a[1], aF0[1] + so);
        #pragma unroll
        for (int g = 0; g < 4; g++) {
            uint32_t bh[4];
            ldm_x4(bh, bF0 + so + g * 16 * 48);
            #pragma unroll
            for (int h = 0; h < 2; h++) {
                int ni = g * 2 + h;
                mma16(acc[0][ni], a[0], bh[2 * h], bh[2 * h + 1]);
                mma16(acc[1][ni], a[1], bh[2 * h], bh[2 * h + 1]);
            }
        }
        stage = (stage + 1 == STAGES) ? 0 : stage + 1;
        pstage = (pstage + 1 == STAGES) ? 0 : pstage + 1;
    }

    if (n0 < 512) {
        #pragma unroll
        for (int mi = 0; mi < 2; mi++) {
            int r0o = m0 + wm + mi * 16 + lq;
            #pragma unroll
            for (int ni = 0; ni < 8; ni++) {
                int c = n0 + wn + ni * 8 + lr * 2;
                float bv0 = bias[c], bv1 = bias[c + 1];
                *reinterpret_cast<float2*>(&S[(size_t)r0o * 512 + c]) =
                    {acc[mi][ni][0] + bv0, acc[mi][ni][1] + bv1};
                *reinterpret_cast<float2*>(&S[(size_t)(r0o + 8) * 512 + c]) =
                    {acc[mi][ni][2] + bv0, acc[mi][ni][3] + bv1};
            }
        }
    } else {
        double qp = 0.0;
        #pragma unroll
        for (int mi = 0; mi < 2; mi++) {
            int r0o = m0 + wm + mi * 16 + lq;
            #pragma unroll
            for (int ni = 0; ni < 8; ni++) {
                int cg = (n0 - 512) + wn + ni * 8 + lr * 2;
                int p = cg >> 1;
                float bv0 = bias[512 + cg], bv1 = bias[512 + cg + 1];
                #pragma unroll
                for (int rr = 0; rr < 2; rr++) {
                    int r = r0o + rr * 8;
                    uint32_t uh = g_h1hi[(size_t)r * 512 + p];
                    uint32_t ul = g_h1lo[(size_t)r * 512 + p];
                    float2 fh = __half22float2(*reinterpret_cast<__half2*>(&uh));
                    float2 fl = __half22float2(*reinterpret_cast<__half2*>(&ul));
                    qp += (double)((acc[mi][ni][rr * 2] + bv0) * (fh.x + fl.x))
                        + (double)((acc[mi][ni][rr * 2 + 1] + bv1) * (fh.y + fl.y));
                }
            }
        }
        #pragma unroll
        for (int o = 16; o; o >>= 1) qp += __shfl_xor_sync(0xFFFFFFFFu, qp, o);
        if (lane == 0) qred[wid] = qp;
        __syncthreads();
        if (tid == 0) {
            double t = 0.0;
            #pragma unroll
            for (int i = 0; i < 8; i++) t += qred[i];
            atomicAdd(&g_sum, t);
        }
    }
}

// ---------- per-row top-2 argmin + flags + v1 accumulation --------
__global__ void argmin_kernel(float* __restrict__ out_ind_f) {
    __shared__ double s_v[8];
    int warp = threadIdx.x >> 5;
    int lane = threadIdx.x & 31;
    int b = blockIdx.x * 8 + warp;

    const float* su = g_S + (size_t)b * 512;

    float v1 = FLT_MAX, v2 = FLT_MAX;
    int   k1 = -1, k2 = -1;
    for (int k = lane; k < NUM_EMB; k += 32) {
        float v = g_e2[k] - 2.f * su[k];
        if (v < v1 || (v == v1 && k < k1)) { v2 = v1; k2 = k1; v1 = v; k1 = k; }
        else if (v < v2 || (v == v2 && k < k2)) { v2 = v; k2 = k; }
    }
    #pragma unroll
    for (int o = 16; o; o >>= 1) {
        float ov1 = __shfl_xor_sync(0xFFFFFFFFu, v1, o);
        int   ok1 = __shfl_xor_sync(0xFFFFFFFFu, k1, o);
        float ov2 = __shfl_xor_sync(0xFFFFFFFFu, v2, o);
        int   ok2 = __shfl_xor_sync(0xFFFFFFFFu, k2, o);
        if (!(ov1 == v1 && ok1 == k1)) {
            if (ov1 < v1 || (ov1 == v1 && ok1 < k1)) { v2 = v1; k2 = k1; v1 = ov1; k1 = ok1; }
            else if (ov1 < v2 || (ov1 == v2 && ok1 < k2)) { v2 = ov1; k2 = ok1; }
        }
        if (!(ov2 == v1 && ok2 == k1)) {
            if (ov2 < v1 || (ov2 == v1 && ok2 < k1)) { v2 = v1; k2 = k1; v1 = ov2; k1 = ok2; }
            else if (ov2 < v2 || (ov2 == v2 && ok2 < k2)) { v2 = ov2; k2 = ok2; }
        }
    }
    if (lane == 0) {
        g_ind[b] = k1;
        out_ind_f[b] = (float)k1;
        s_v[warp] = (double)v1;
        if (v2 - v1 < MARGIN && k2 >= 0) {
            int idx = atomicAdd(&g_nflag, 1);
            if (idx < MAXFLAG) {
                g_fb[idx] = b; g_fk1[idx] = k1; g_fk2[idx] = k2;
            }
        }
    }
    __syncthreads();
    if (threadIdx.x == 0) {
        double t = 0.0;
        #pragma unroll
        for (int i = 0; i < 8; i++) t += s_v[i];
        atomicAdd(&g_sum, t);
    }
}

// ----- refinement via M (fp64): one warp per flagged row -----
__global__ void refine_kernel(float* __restrict__ out_ind_f) {
    int nf = g_nflag; if (nf > MAXFLAG) nf = MAXFLAG;
    int f = (blockIdx.x * 256 + threadIdx.x) >> 5;
    int lane = threadIdx.x & 31;
    if (f >= nf) return;
    int b = g_fb[f];
    int k1 = g_fk1[f], k2 = g_fk2[f];
    const float* m1 = g_MGT + (size_t)k1 * CH;
    const float* m2 = g_MGT + (size_t)k2 * CH;
    double s = 0.0;
    for (int p = lane; p < 256; p += 32) {
        uint32_t uh = g_h1hi[(size_t)b * 512 + p];
        uint32_t ul = g_h1lo[(size_t)b * 512 + p];
        float2 fh = __half22float2(*reinterpret_cast<__half2*>(&uh));
        float2 fl = __half22float2(*reinterpret_cast<__half2*>(&ul));
        double h0 = (double)fh.x + (double)fl.x;
        double h1 = (double)fh.y + (double)fl.y;
        int j = p * 2;
        s += h0 * ((double)m2[j] - (double)m1[j]);
        s += h1 * ((double)m2[j + 1] - (double)m1[j + 1]);
    }
    #pragma unroll
    for (int o = 16; o; o >>= 1) s += __shfl_xor_sync(0xFFFFFFFFu, s, o);
    if (lane == 0) {
        double delta = (g_e2d[k2] - g_e2d[k1]) - 2.0 * (s + (g_cd[k2] - g_cd[k1]));
        if (delta < 0.0 || (delta == 0.0 && k2 < k1)) {
            g_ind[b] = k2;
            out_ind_f[b] = (float)k2;
        }
    }
}

// ---------------- per-sample expert MLP decode ----------------
__global__ void decoder_kernel(const float* __restrict__ W1, const float* __restrict__ b1,
                               const float* __restrict__ W2, const float* __restrict__ b2,
                               float* __restrict__ out) {
    __shared__ float exs[8][64];
    __shared__ float hs [8][64];
    int warp = threadIdx.x >> 5;
    int lane = threadIdx.x & 31;
    int b = blockIdx.x * 8 + warp;

    exs[warp][lane]      = g_expad[(size_t)b * 128 + lane];
    exs[warp][lane + 32] = g_expad[(size_t)b * 128 + lane + 32];
    __syncwarp();

    int k = g_ind[b];
    const float* w1 = W1 + (size_t)k * 64 * 64;
    float h0 = b1[k * 64 + lane];
    float h1 = b1[k * 64 + lane + 32];
    #pragma unroll 8
    for (int i = 0; i < 64; i++) {
        float xi = exs[warp][i];
        h0 += xi * w1[i * 64 + lane];
        h1 += xi * w1[i * 64 + lane + 32];
    }
    hs[warp][lane]      = fmaxf(h0, 0.f);
    hs[warp][lane + 32] = fmaxf(h1, 0.f);
    __syncwarp();

    const float* w2 = W2 + (size_t)k * 64 * 32;
    float o = b2[k * 32 + lane];
    #pragma unroll 8
    for (int i = 0; i < 64; i++)
        o += hs[warp][i] * w2[i * 32 + lane];
    out[(size_t)b * 32 + lane] = o;
}

// ---------------- finalize: counts + diff + perplexity ----------------
__global__ void finalize_kernel(float* __restrict__ out) {
    __shared__ int hist[512];
    __shared__ float red[512];
    int k = threadIdx.x;
    hist[k] = 0;
    __syncthreads();
    for (int i = k; i < BATCH; i += 512)
        atomicAdd(&hist[g_ind[i]], 1);
    __syncthreads();
    float p = (float)hist[k] / (float)BATCH;
    red[k] = -p * logf(p + 1e-10f);
    __syncthreads();
    for (int s = 256; s; s >>= 1) {
        if (k < s) red[k] += red[k + s];
        __syncthreads();
    }
    if (k == 0) {
        double total = g_sum + (double)BATCH * (double)g_beta;
        out[OUT_DIFF] = (float)(total / ((double)BATCH * (double)EMBED_D));
        out[OUT_PERP] = expf(red[0]);
    }
}

// ---------------- launch ----------------
extern "C" void kernel_launch(void* const* d_in, const int* in_sizes, int n_in,
                              void* d_out, int out_size) {
    const float* x     = (const float*)d_in[0];
    const float* Wf1   = (const float*)d_in[1];
    const float* bf1   = (const float*)d_in[2];
    const float* Wf2   = (const float*)d_in[3];
    const float* bf2   = (const float*)d_in[4];
    const float* Wx1   = (const float*)d_in[5];
    const float* bx1   = (const float*)d_in[6];
    const float* Wx2   = (const float*)d_in[7];
    const float* bx2   = (const float*)d_in[8];
    const float* embed = (const float*)d_in[9];
    const float* W1    = (const float*)d_in[10];
    const float* b1    = (const float*)d_in[11];
    const float* W2    = (const float*)d_in[12];
    const float* b2    = (const float*)d_in[13];
    float* out = (float*)d_out;

    void *p_h1hi, *p_h1lo, *p_S, *p_expad, *p_MGThi, *p_bias2, *p_part,
         *p_BcatTh, *p_BcatTl, *p_Wf2h, *p_Wf2l, *p_xh, *p_xl,
         *p_B1h, *p_B1l, *p_Wx2h, *p_Wx2l, *p_biascat1, *p_bx2pad;
    cudaGetSymbolAddress(&p_h1hi, g_h1hi);
    cudaGetSymbolAddress(&p_h1lo, g_h1lo);
    cudaGetSymbolAddress(&p_S,    g_S);
    cudaGetSymbolAddress(&p_expad,g_expad);
    cudaGetSymbolAddress(&p_MGThi,g_MGThi);
    cudaGetSymbolAddress(&p_bias2,g_bias2);
    cudaGetSymbolAddress(&p_part, g_part);
    cudaGetSymbolAddress(&p_BcatTh, g_BcatTh);
    cudaGetSymbolAddress(&p_BcatTl, g_BcatTl);
    cudaGetSymbolAddress(&p_Wf2h, g_Wf2h);
    cudaGetSymbolAddress(&p_Wf2l, g_Wf2l);
    cudaGetSymbolAddress(&p_xh,   g_xh);
    cudaGetSymbolAddress(&p_xl,   g_xl);
    cudaGetSymbolAddress(&p_B1h,  g_B1h);
    cudaGetSymbolAddress(&p_B1l,  g_B1l);
    cudaGetSymbolAddress(&p_Wx2h, g_Wx2h);
    cudaGetSymbolAddress(&p_Wx2l, g_Wx2l);
    cudaGetSymbolAddress(&p_biascat1, g_biascat1);
    cudaGetSymbolAddress(&p_bx2pad,   g_bx2pad);

    cudaFuncSetAttribute((const void*)hgemm<true, 3, 0, false, false, true>,
                         cudaFuncAttributeMaxDynamicSharedMemorySize, SMEM_X3);
    cudaFuncSetAttribute((const void*)hgemm<false, 4, 0, false, false, true>,
                         cudaFuncAttributeMaxDynamicSharedMemorySize, SMEM_1X);
    cudaFuncSetAttribute((const void*)hgemm<true, 3, 1, true, true, false>,
                         cudaFuncAttributeMaxDynamicSharedMemorySize, SMEM_X3);
    cudaFuncSetAttribute((const void*)hgemm<true, 3, 0, true, false, false>,
                         cudaFuncAttributeMaxDynamicSharedMemorySize, SMEM_X3);
    cudaFuncSetAttribute((const void*)su16q_kernel,
                         cudaFuncAttributeMaxDynamicSharedMemorySize, SMEM_1X);

    // side stream + events; fork/join strictly via events on the captured
    // stream (R14-proven pattern): never launch on s1 before it waits on an
    // event recorded in stream 0.
    cudaStream_t s1;
    cudaStreamCreateWithFlags(&s1, cudaStreamNonBlocking);
    cudaEvent_t evA, evP;
    cudaEventCreateWithFlags(&evA, cudaEventDisableTiming);
    cudaEventCreateWithFlags(&evP, cudaEventDisableTiming);

    // ---- main stream: prep1 first (captured root) ----
    prep1_kernel<<<J_TOT, 256>>>(embed, Wf2, Wf1, Wx1, bf1, bx1, Wx2, bx2);
    cudaEventRecord(evA, 0);
    cudaStreamWaitEvent(s1, evA, 0);

    // ---- side stream: fp64 scalar prep (disjoint pipes vs tensor chain) ----
    prep2_kernel<<<NCHUNKD + 160 + 1, 512, 0, s1>>>(embed, Wf2, bf2);
    prep3_kernel<<<1, 1024, 0, s1>>>();
    cudaEventRecord(evP, s1);

    // ---- main stream: tensor chain ----
    xsplit_kernel<<<BATCH * IN_C / 4 / 256, 256>>>(x);

    // MGT rows [0,512) = M : x3 (fp32-grade, refine oracle needs it)
    hgemm<true, 3, 0, false, false, true><<<dim3(4, 4, NSPLIT), 256, SMEM_X3>>>(
        (const __half*)p_BcatTh, (const __half*)p_BcatTl,
        (const __half*)p_Wf2h, (const __half*)p_Wf2l,
        nullptr, (float*)p_part, nullptr,
        1024, CH, EMBED_D, EMBED_D, EMBED_D, CH, 0);
    // MGT rows [512,1024) = G : 1x (feeds only the diff scalar)
    hgemm<false, 4, 0, false, false, true><<<dim3(4, 4, NSPLIT), 256, SMEM_1X>>>(
        (const __half*)p_BcatTh, nullptr,
        (const __half*)p_Wf2h, nullptr,
        nullptr, (float*)p_part, nullptr,
        1024, CH, EMBED_D, EMBED_D, EMBED_D, CH, 512);
    mgt_reduce_kernel<<<1024 * 256 / 256, 256>>>();

    // h1cat = relu(x @ [Wf1|Wx1] + b) -> hi/lo halves
    hgemm<true, 3, 1, true, true, false><<<dim3(8, 128), 256, SMEM_X3>>>(
        (const __half*)p_xh, (const __half*)p_xl,
        (const __half*)p_B1h, (const __half*)p_B1l,
        (const float*)p_biascat1, (float*)p_h1hi, (float*)p_h1lo,
        BATCH, 1024, IN_C, IN_C, IN_C, 512, 0);

    // join: su16q needs g_bias2/g_e2 from prep3
    cudaStreamWaitEvent(0, evP, 0);

    // s = h1@M + c ; Σq via u-blocks
    su16q_kernel<<<dim3(8, 128), 256, SMEM_1X>>>(
        (const __half*)p_h1hi, (const __half*)p_MGThi,
        (const float*)p_bias2, (float*)p_S);

    // ex = h1x @ Wx2 + bx2  (x3, N padded 128)
    hgemm<true, 3, 0, true, false, false><<<dim3(1, 128), 256, SMEM_X3>>>(
        (const __half*)p_h1hi + 512, (const __half*)p_h1lo + 512,
        (const __half*)p_Wx2h, (const __half*)p_Wx2l,
        (const float*)p_bx2pad, (float*)p_expad, nullptr,
        BATCH, 128, CH, 1024, CH, 128, 0);

    argmin_kernel<<<BATCH / 8, 256>>>(out + OUT_IND);
    refine_kernel<<<MAXFLAG / 8, 256>>>(out + OUT_IND);
    decoder_kernel<<<BATCH / 8, 256>>>(W1, b1, W2, b2, out);
    finalize_kernel<<<1, 512>>>(out);
}